// round 1
// baseline (speedup 1.0000x reference)
#include <cuda_runtime.h>
#include <math.h>

#define NN 100000
#define EE 800000
#define ETOT 900000   // EE + NN self loops

// ---------------- device scratch (no cudaMalloc allowed) ----------------
__device__ int   g_is64;
__device__ float g_h1feat[NN * 256];   // layer1 per-head features [N, 8*32]
__device__ float g_as1[NN * 8];
__device__ float g_ad1[NN * 8];
__device__ float g_z1[NN * 8];
__device__ float g_out1[NN * 32];      // sum over heads of aggregated feats
__device__ float g_h1[NN * 32];        // relu(mean + b1)
__device__ float g_h2feat[NN * 128];   // layer2 per-head features [N, 8*16]
__device__ float g_as2[NN * 8];
__device__ float g_ad2[NN * 8];
__device__ float g_z2[NN * 8];
__device__ float g_out2[NN * 16];
__device__ float g_alpha1s[ETOT * 8];  // scratch alphas (logits-only mode)
__device__ float g_alpha2s[ETOT * 8];

// ---------------- int64/int32 edge-index autodetect ----------------
__global__ void k_detect(const void* ei) {
    if (blockIdx.x == 0 && threadIdx.x == 0) {
        const long long* p = (const long long*)ei;
        int ok = 1;
        for (int i = 0; i < 8; i++) {
            long long v = p[i];
            if (v < 0 || v >= NN) ok = 0;
        }
        g_is64 = ok;
    }
}

__device__ __forceinline__ int ld_idx(const void* ei, long long pos) {
    if (g_is64) return (int)((const long long*)ei)[pos];
    return ((const int*)ei)[pos];
}

__global__ void k_zero() {
    int i = blockIdx.x * blockDim.x + threadIdx.x;
    if (i < NN * 8)  { g_z1[i] = 0.f; g_z2[i] = 0.f; }
    if (i < NN * 32)   g_out1[i] = 0.f;
    if (i < NN * 16)   g_out2[i] = 0.f;
}

// ---------------- generic SGEMM: C[M,Nc] = A[M,K] * B[Nc,K]^T ----------------
// BM=BN=64, BK=16, 256 threads, 4x4 per-thread tile, float4 I/O.
__global__ void sgemm_nt(const float* __restrict__ A, const float* __restrict__ B,
                         float* __restrict__ C, int M, int Nc, int K) {
    __shared__ float As[16][65];
    __shared__ float Bs[16][65];
    int bm = blockIdx.y * 64, bn = blockIdx.x * 64;
    int tid = threadIdx.x;
    int tx = tid & 15, ty = tid >> 4;
    int ar = tid >> 2, ac = (tid & 3) << 2;

    float acc[4][4];
#pragma unroll
    for (int i = 0; i < 4; i++)
#pragma unroll
        for (int j = 0; j < 4; j++) acc[i][j] = 0.f;

    for (int k0 = 0; k0 < K; k0 += 16) {
        float4 av = make_float4(0.f, 0.f, 0.f, 0.f);
        int arow = bm + ar;
        if (arow < M) av = *(const float4*)(A + (size_t)arow * K + k0 + ac);
        As[ac + 0][ar] = av.x; As[ac + 1][ar] = av.y;
        As[ac + 2][ar] = av.z; As[ac + 3][ar] = av.w;
        float4 bv = *(const float4*)(B + (size_t)(bn + ar) * K + k0 + ac);
        Bs[ac + 0][ar] = bv.x; Bs[ac + 1][ar] = bv.y;
        Bs[ac + 2][ar] = bv.z; Bs[ac + 3][ar] = bv.w;
        __syncthreads();
#pragma unroll
        for (int k = 0; k < 16; k++) {
            float a[4], b[4];
#pragma unroll
            for (int i = 0; i < 4; i++) a[i] = As[k][(ty << 2) + i];
#pragma unroll
            for (int j = 0; j < 4; j++) b[j] = Bs[k][(tx << 2) + j];
#pragma unroll
            for (int i = 0; i < 4; i++)
#pragma unroll
                for (int j = 0; j < 4; j++) acc[i][j] += a[i] * b[j];
        }
        __syncthreads();
    }
#pragma unroll
    for (int i = 0; i < 4; i++) {
        int row = bm + (ty << 2) + i;
        if (row < M) {
            float4 v = make_float4(acc[i][0], acc[i][1], acc[i][2], acc[i][3]);
            *(float4*)(C + (size_t)row * Nc + bn + (tx << 2)) = v;
        }
    }
}

// ---------------- per-(node,head) attention coefficients ----------------
__global__ void k_attn(const float* __restrict__ feat, const float* __restrict__ a_src,
                       const float* __restrict__ a_dst, float* __restrict__ as_,
                       float* __restrict__ ad_, int F) {
    int i = blockIdx.x * blockDim.x + threadIdx.x;   // i = n*8 + h
    if (i >= NN * 8) return;
    int h = i & 7;
    const float* fp = feat + (size_t)i * F;
    const float* sp = a_src + h * F;
    const float* dp = a_dst + h * F;
    float vs = 0.f, vd = 0.f;
#pragma unroll 8
    for (int f = 0; f < F; f++) {
        float v = fp[f];
        vs += v * sp[f];
        vd += v * dp[f];
    }
    as_[i] = vs;
    ad_[i] = vd;
}

// ---------------- pass B: p = exp(leakyrelu(as[src]+ad[dst])), z[dst] += p ----------------
__global__ void k_passB(const void* ei, const float* __restrict__ as_,
                        const float* __restrict__ ad_, float* __restrict__ alpha,
                        float* __restrict__ z) {
    int e = blockIdx.x * blockDim.x + threadIdx.x;
    if (e >= ETOT) return;
    int s, d;
    if (e < EE) { s = ld_idx(ei, e); d = ld_idx(ei, EE + e); }
    else        { s = e - EE; d = s; }
    const float* ap = as_ + (size_t)s * 8;
    const float* dp = ad_ + (size_t)d * 8;
    float p[8];
#pragma unroll
    for (int h = 0; h < 8; h++) {
        float x = ap[h] + dp[h];
        x = x > 0.f ? x : 0.2f * x;       // LeakyReLU(0.2)
        p[h] = __expf(x);                  // softmax shift-invariant; e is O(0.1)
    }
#pragma unroll
    for (int h = 0; h < 8; h++) alpha[(size_t)e * 8 + h] = p[h];
    float* zp = z + (size_t)d * 8;
#pragma unroll
    for (int h = 0; h < 8; h++) atomicAdd(zp + h, p[h]);
}

// ---------------- pass C: alpha = p/(z+eps); out[dst] += sum_h alpha_h * h[src,h,:] ----------------
// one warp per edge; lane = feature index
template <int F>
__global__ void k_passC(const void* ei, const float* __restrict__ feat,
                        const float* __restrict__ z, float* __restrict__ alpha,
                        float* __restrict__ outacc) {
    int e = (blockIdx.x * blockDim.x + threadIdx.x) >> 5;
    int lane = threadIdx.x & 31;
    if (e >= ETOT) return;
    int s, d;
    if (e < EE) { s = ld_idx(ei, e); d = ld_idx(ei, EE + e); }
    else        { s = e - EE; d = s; }
    float a = 0.f;
    if (lane < 8) {
        float p = alpha[(size_t)e * 8 + lane];
        float zz = z[(size_t)d * 8 + lane];
        a = p / (zz + 1e-16f);
        alpha[(size_t)e * 8 + lane] = a;
    }
    float ah[8];
#pragma unroll
    for (int h = 0; h < 8; h++) ah[h] = __shfl_sync(0xffffffffu, a, h);
    if (lane < F) {
        const float* fp = feat + (size_t)s * (8 * F);
        float acc = 0.f;
#pragma unroll
        for (int h = 0; h < 8; h++) acc += ah[h] * fp[h * F + lane];
        atomicAdd(outacc + (size_t)d * F + lane, acc);
    }
}

// ---------------- finalize layer 1: h1 = relu(mean_h + b1) ----------------
__global__ void k_fin1(const float* __restrict__ b1) {
    int i = blockIdx.x * blockDim.x + threadIdx.x;
    if (i >= NN * 32) return;
    float v = g_out1[i] * 0.125f + b1[i & 31];
    g_h1[i] = v > 0.f ? v : 0.f;
}

// ---------------- finalize layer 2: log_softmax(mean_h + b2) ----------------
__global__ void k_fin2(const float* __restrict__ b2, float* __restrict__ outlog) {
    int n = blockIdx.x * blockDim.x + threadIdx.x;
    if (n >= NN) return;
    float v[16];
    float m = -1e30f;
#pragma unroll
    for (int j = 0; j < 16; j++) {
        v[j] = g_out2[n * 16 + j] * 0.125f + b2[j];
        m = fmaxf(m, v[j]);
    }
    float sum = 0.f;
#pragma unroll
    for (int j = 0; j < 16; j++) sum += expf(v[j] - m);
    float lse = m + logf(sum);
#pragma unroll
    for (int j = 0; j < 16; j++) outlog[n * 16 + j] = v[j] - lse;
}

// ---------------- emit ei_loops as float ----------------
__global__ void k_ei(const void* ei, float* __restrict__ o) {
    int i = blockIdx.x * blockDim.x + threadIdx.x;
    if (i >= 2 * ETOT) return;
    int row = i / ETOT;
    int e = i - row * ETOT;
    long long v;
    if (e < EE) v = ld_idx(ei, (long long)row * EE + e);
    else        v = e - EE;
    o[i] = (float)v;
}

// ---------------- host launcher ----------------
extern "C" void kernel_launch(void* const* d_in, const int* in_sizes, int n_in,
                              void* d_out, int out_size) {
    const float* x    = (const float*)d_in[0];
    const void*  ei   = d_in[1];
    const float* W1   = (const float*)d_in[2];
    const float* aS1  = (const float*)d_in[3];
    const float* aD1  = (const float*)d_in[4];
    const float* b1   = (const float*)d_in[5];
    const float* W2   = (const float*)d_in[6];
    const float* aS2  = (const float*)d_in[7];
    const float* aD2  = (const float*)d_in[8];
    const float* b2   = (const float*)d_in[9];
    float* out = (float*)d_out;

    const long long SZ_LOG = (long long)NN * 16;        // 1,600,000
    const long long SZ_EI  = 2LL * ETOT;                // 1,800,000
    const long long SZ_A   = (long long)ETOT * 8;       // 7,200,000
    const long long FULL   = SZ_LOG + SZ_EI + 2 * SZ_A; // 17,800,000
    bool full = ((long long)out_size >= FULL);

    void* vp;
    float *h1feat, *as1p, *ad1p, *z1p, *out1p, *h1p;
    float *h2feat, *as2p, *ad2p, *z2p, *out2p;
    cudaGetSymbolAddress(&vp, g_h1feat); h1feat = (float*)vp;
    cudaGetSymbolAddress(&vp, g_as1);    as1p   = (float*)vp;
    cudaGetSymbolAddress(&vp, g_ad1);    ad1p   = (float*)vp;
    cudaGetSymbolAddress(&vp, g_z1);     z1p    = (float*)vp;
    cudaGetSymbolAddress(&vp, g_out1);   out1p  = (float*)vp;
    cudaGetSymbolAddress(&vp, g_h1);     h1p    = (float*)vp;
    cudaGetSymbolAddress(&vp, g_h2feat); h2feat = (float*)vp;
    cudaGetSymbolAddress(&vp, g_as2);    as2p   = (float*)vp;
    cudaGetSymbolAddress(&vp, g_ad2);    ad2p   = (float*)vp;
    cudaGetSymbolAddress(&vp, g_z2);     z2p    = (float*)vp;
    cudaGetSymbolAddress(&vp, g_out2);   out2p  = (float*)vp;

    float *alpha1, *alpha2;
    if (full) {
        alpha1 = out + SZ_LOG + SZ_EI;
        alpha2 = alpha1 + SZ_A;
    } else {
        cudaGetSymbolAddress(&vp, g_alpha1s); alpha1 = (float*)vp;
        cudaGetSymbolAddress(&vp, g_alpha2s); alpha2 = (float*)vp;
    }

    k_detect<<<1, 32>>>(ei);
    k_zero<<<(NN * 32 + 255) / 256, 256>>>();

    // layer 1
    {
        dim3 g(256 / 64, (NN + 63) / 64);
        sgemm_nt<<<g, 256>>>(x, W1, h1feat, NN, 256, 128);
    }
    k_attn<<<(NN * 8 + 255) / 256, 256>>>(h1feat, aS1, aD1, as1p, ad1p, 32);
    k_passB<<<(ETOT + 255) / 256, 256>>>(ei, as1p, ad1p, alpha1, z1p);
    k_passC<32><<<(ETOT * 32 + 255) / 256, 256>>>(ei, h1feat, z1p, alpha1, out1p);
    k_fin1<<<(NN * 32 + 255) / 256, 256>>>(b1);

    // layer 2
    {
        dim3 g(128 / 64, (NN + 63) / 64);
        sgemm_nt<<<g, 256>>>(h1p, W2, h2feat, NN, 128, 32);
    }
    k_attn<<<(NN * 8 + 255) / 256, 256>>>(h2feat, aS2, aD2, as2p, ad2p, 16);
    k_passB<<<(ETOT + 255) / 256, 256>>>(ei, as2p, ad2p, alpha2, z2p);
    k_passC<16><<<(ETOT * 32 + 255) / 256, 256>>>(ei, h2feat, z2p, alpha2, out2p);
    k_fin2<<<(NN + 255) / 256, 256>>>(b2, out);

    if (full) k_ei<<<(2 * ETOT + 255) / 256, 256>>>(ei, out + SZ_LOG);
}

// round 4
// speedup vs baseline: 1.4036x; 1.4036x over previous
#include <cuda_runtime.h>
#include <math.h>

#define NN 100000
#define EE 800000
#define ETOT 900000   // EE + NN self loops

// ---------------- device scratch (no cudaMalloc allowed) ----------------
__device__ int   g_is64;
__device__ float g_h1feat[NN * 256];   // layer1 per-head features [N, 8*32]
__device__ float g_as1[NN * 8];
__device__ float g_ad1[NN * 8];
__device__ float g_z1[NN * 8];
__device__ float g_out1[NN * 32];
__device__ float g_h1[NN * 32];
__device__ float g_h2feat[NN * 128];   // layer2 per-head features [N, 8*16]
__device__ float g_as2[NN * 8];
__device__ float g_ad2[NN * 8];
__device__ float g_z2[NN * 8];
__device__ float g_out2[NN * 16];
__device__ float g_alpha1s[ETOT * 8];
__device__ float g_alpha2s[ETOT * 8];

// ---------------- int64/int32 edge-index autodetect ----------------
__global__ void k_detect(const void* ei) {
    if (blockIdx.x == 0 && threadIdx.x == 0) {
        const long long* p = (const long long*)ei;
        int ok = 1;
        for (int i = 0; i < 8; i++) {
            long long v = p[i];
            if (v < 0 || v >= NN) ok = 0;
        }
        g_is64 = ok;
    }
}

__device__ __forceinline__ int ld_idx(const void* ei, long long pos) {
    if (g_is64) return (int)((const long long*)ei)[pos];
    return ((const int*)ei)[pos];
}

__global__ void k_zero() {
    int i = blockIdx.x * blockDim.x + threadIdx.x;
    if (i < NN * 8)  { g_z1[i] = 0.f; g_z2[i] = 0.f; }
    if (i < NN * 32)   g_out1[i] = 0.f;
    if (i < NN * 16)   g_out2[i] = 0.f;
}

// ---------------- SGEMM: C[M,Nc] = A[M,K] * B[Nc,K]^T ----------------
// BM=128, BN=64, BK=16, 256 threads, 8x4 per-thread microtile.
__global__ __launch_bounds__(256) void sgemm_nt(
        const float* __restrict__ A, const float* __restrict__ B,
        float* __restrict__ C, int M, int Nc, int K) {
    __shared__ float As[16][132];   // [k][row]
    __shared__ float Bs[16][68];    // [k][col]
    int bm = blockIdx.y * 128, bn = blockIdx.x * 64;
    int tid = threadIdx.x;
    int tx = tid & 15;              // col group (4 cols)
    int ty = tid >> 4;              // row group (8 rows)

    float acc[8][4];
#pragma unroll
    for (int i = 0; i < 8; i++)
#pragma unroll
        for (int j = 0; j < 4; j++) acc[i][j] = 0.f;

    for (int k0 = 0; k0 < K; k0 += 16) {
        // load A tile: 128 rows x 16 k = 512 float4; 2 per thread
#pragma unroll
        for (int t = 0; t < 2; t++) {
            int f = tid * 2 + t;
            int r = f >> 2, kc = (f & 3) << 2;
            float4 v = make_float4(0.f, 0.f, 0.f, 0.f);
            int arow = bm + r;
            if (arow < M) v = *(const float4*)(A + (size_t)arow * K + k0 + kc);
            As[kc + 0][r] = v.x; As[kc + 1][r] = v.y;
            As[kc + 2][r] = v.z; As[kc + 3][r] = v.w;
        }
        // load B tile: 64 rows x 16 k = 256 float4; 1 per thread
        {
            int r = tid >> 2, kc = (tid & 3) << 2;
            float4 v = *(const float4*)(B + (size_t)(bn + r) * K + k0 + kc);
            Bs[kc + 0][r] = v.x; Bs[kc + 1][r] = v.y;
            Bs[kc + 2][r] = v.z; Bs[kc + 3][r] = v.w;
        }
        __syncthreads();
#pragma unroll
        for (int k = 0; k < 16; k++) {
            float a[8], b[4];
            float4 a0 = *(const float4*)&As[k][ty * 8];
            float4 a1 = *(const float4*)&As[k][ty * 8 + 4];
            a[0] = a0.x; a[1] = a0.y; a[2] = a0.z; a[3] = a0.w;
            a[4] = a1.x; a[5] = a1.y; a[6] = a1.z; a[7] = a1.w;
            float4 bv = *(const float4*)&Bs[k][tx * 4];
            b[0] = bv.x; b[1] = bv.y; b[2] = bv.z; b[3] = bv.w;
#pragma unroll
            for (int i = 0; i < 8; i++)
#pragma unroll
                for (int j = 0; j < 4; j++) acc[i][j] += a[i] * b[j];
        }
        __syncthreads();
    }
#pragma unroll
    for (int i = 0; i < 8; i++) {
        int row = bm + ty * 8 + i;
        if (row < M) {
            float4 v = make_float4(acc[i][0], acc[i][1], acc[i][2], acc[i][3]);
            *(float4*)(C + (size_t)row * Nc + bn + tx * 4) = v;
        }
    }
}

// ---------------- attention coefficients (coalesced float4 + butterfly) ----------------
// G = F/4 threads per (node,head) pair. LG2G = log2(G).
template <int F, int LG2G>
__global__ __launch_bounds__(256) void k_attn2(
        const float4* __restrict__ feat4,
        const float* __restrict__ a_src,
        const float* __restrict__ a_dst,
        float* __restrict__ as_, float* __restrict__ ad_) {
    constexpr int G = F / 4;          // 8 (F=32) or 4 (F=16)
    constexpr int P = 256 / G;        // pairs per block
    __shared__ float4 sa[8 * G], sd[8 * G];
    int tid = threadIdx.x;
    if (tid < 8 * G) {
        sa[tid] = ((const float4*)a_src)[tid];
        sd[tid] = ((const float4*)a_dst)[tid];
    }
    __syncthreads();
    int pair = blockIdx.x * P + (tid >> LG2G);   // = n*8 + h
    int g = tid & (G - 1);
    bool ok = (pair < NN * 8);
    int h = pair & 7;
    float4 v = make_float4(0.f, 0.f, 0.f, 0.f);
    if (ok) v = feat4[(size_t)pair * G + g];
    float4 A = sa[h * G + g], D = sd[h * G + g];
    float vs = v.x * A.x + v.y * A.y + v.z * A.z + v.w * A.w;
    float vd = v.x * D.x + v.y * D.y + v.z * D.z + v.w * D.w;
#pragma unroll
    for (int off = G / 2; off > 0; off >>= 1) {
        vs += __shfl_xor_sync(0xffffffffu, vs, off);
        vd += __shfl_xor_sync(0xffffffffu, vd, off);
    }
    if (ok && g == 0) { as_[pair] = vs; ad_[pair] = vd; }
}

// ---------------- pass B ----------------
__global__ void k_passB(const void* ei, const float* __restrict__ as_,
                        const float* __restrict__ ad_, float* __restrict__ alpha,
                        float* __restrict__ z) {
    int e = blockIdx.x * blockDim.x + threadIdx.x;
    if (e >= ETOT) return;
    int s, d;
    if (e < EE) { s = ld_idx(ei, e); d = ld_idx(ei, EE + e); }
    else        { s = e - EE; d = s; }
    const float* ap = as_ + (size_t)s * 8;
    const float* dp = ad_ + (size_t)d * 8;
    float p[8];
#pragma unroll
    for (int h = 0; h < 8; h++) {
        float x = ap[h] + dp[h];
        x = x > 0.f ? x : 0.2f * x;
        p[h] = __expf(x);
    }
#pragma unroll
    for (int h = 0; h < 8; h++) alpha[(size_t)e * 8 + h] = p[h];
    float* zp = z + (size_t)d * 8;
#pragma unroll
    for (int h = 0; h < 8; h++) atomicAdd(zp + h, p[h]);
}

// ---------------- pass C, F=32: warp per edge ----------------
__global__ void k_passC32(const void* ei, const float* __restrict__ feat,
                          const float* __restrict__ z, float* __restrict__ alpha,
                          float* __restrict__ outacc) {
    int e = (blockIdx.x * blockDim.x + threadIdx.x) >> 5;
    int lane = threadIdx.x & 31;
    if (e >= ETOT) return;
    int s, d;
    if (e < EE) { s = ld_idx(ei, e); d = ld_idx(ei, EE + e); }
    else        { s = e - EE; d = s; }
    float a = 0.f;
    if (lane < 8) {
        float p = alpha[(size_t)e * 8 + lane];
        float zz = z[(size_t)d * 8 + lane];
        a = p / (zz + 1e-16f);
        alpha[(size_t)e * 8 + lane] = a;
    }
    float ah[8];
#pragma unroll
    for (int h = 0; h < 8; h++) ah[h] = __shfl_sync(0xffffffffu, a, h);
    const float* fp = feat + (size_t)s * 256;
    float acc = 0.f;
#pragma unroll
    for (int h = 0; h < 8; h++) acc += ah[h] * fp[h * 32 + lane];
    atomicAdd(outacc + (size_t)d * 32 + lane, acc);
}

// ---------------- pass C, F=16: two edges per warp (16 lanes each) ----------------
__global__ void k_passC16(const void* ei, const float* __restrict__ feat,
                          const float* __restrict__ z, float* __restrict__ alpha,
                          float* __restrict__ outacc) {
    int gt = blockIdx.x * blockDim.x + threadIdx.x;
    int e = gt >> 4;                 // 16 lanes per edge
    int l = threadIdx.x & 15;
    int sub = (threadIdx.x >> 4) & 1;
    if (e >= ETOT) return;
    int s, d;
    if (e < EE) { s = ld_idx(ei, e); d = ld_idx(ei, EE + e); }
    else        { s = e - EE; d = s; }
    float a = 0.f;
    if (l < 8) {
        float p = alpha[(size_t)e * 8 + l];
        float zz = z[(size_t)d * 8 + l];
        a = p / (zz + 1e-16f);
        alpha[(size_t)e * 8 + l] = a;
    }
    float ah[8];
    int base = sub << 4;
#pragma unroll
    for (int h = 0; h < 8; h++) ah[h] = __shfl_sync(0xffffffffu, a, base + h);
    const float* fp = feat + (size_t)s * 128;
    float acc = 0.f;
#pragma unroll
    for (int h = 0; h < 8; h++) acc += ah[h] * fp[h * 16 + l];
    atomicAdd(outacc + (size_t)d * 16 + l, acc);
}

// ---------------- finalize layer 1 ----------------
__global__ void k_fin1(const float* __restrict__ b1) {
    int i = blockIdx.x * blockDim.x + threadIdx.x;
    if (i >= NN * 32) return;
    float v = g_out1[i] * 0.125f + b1[i & 31];
    g_h1[i] = v > 0.f ? v : 0.f;
}

// ---------------- finalize layer 2: log_softmax ----------------
__global__ void k_fin2(const float* __restrict__ b2, float* __restrict__ outlog) {
    int n = blockIdx.x * blockDim.x + threadIdx.x;
    if (n >= NN) return;
    float v[16];
    float m = -1e30f;
#pragma unroll
    for (int j = 0; j < 16; j++) {
        v[j] = g_out2[n * 16 + j] * 0.125f + b2[j];
        m = fmaxf(m, v[j]);
    }
    float sum = 0.f;
#pragma unroll
    for (int j = 0; j < 16; j++) sum += expf(v[j] - m);
    float lse = m + logf(sum);
#pragma unroll
    for (int j = 0; j < 16; j++) outlog[n * 16 + j] = v[j] - lse;
}

// ---------------- emit ei_loops as float ----------------
__global__ void k_ei(const void* ei, float* __restrict__ o) {
    int i = blockIdx.x * blockDim.x + threadIdx.x;
    if (i >= 2 * ETOT) return;
    int row = i / ETOT;
    int e = i - row * ETOT;
    long long v;
    if (e < EE) v = ld_idx(ei, (long long)row * EE + e);
    else        v = e - EE;
    o[i] = (float)v;
}

// ---------------- host launcher ----------------
extern "C" void kernel_launch(void* const* d_in, const int* in_sizes, int n_in,
                              void* d_out, int out_size) {
    const float* x    = (const float*)d_in[0];
    const void*  ei   = d_in[1];
    const float* W1   = (const float*)d_in[2];
    const float* aS1  = (const float*)d_in[3];
    const float* aD1  = (const float*)d_in[4];
    const float* b1   = (const float*)d_in[5];
    const float* W2   = (const float*)d_in[6];
    const float* aS2  = (const float*)d_in[7];
    const float* aD2  = (const float*)d_in[8];
    const float* b2   = (const float*)d_in[9];
    float* out = (float*)d_out;

    const long long SZ_LOG = (long long)NN * 16;
    const long long SZ_EI  = 2LL * ETOT;
    const long long SZ_A   = (long long)ETOT * 8;
    const long long FULL   = SZ_LOG + SZ_EI + 2 * SZ_A;
    bool full = ((long long)out_size >= FULL);

    void* vp;
    float *h1feat, *as1p, *ad1p, *z1p, *out1p, *h1p;
    float *h2feat, *as2p, *ad2p, *z2p, *out2p;
    cudaGetSymbolAddress(&vp, g_h1feat); h1feat = (float*)vp;
    cudaGetSymbolAddress(&vp, g_as1);    as1p   = (float*)vp;
    cudaGetSymbolAddress(&vp, g_ad1);    ad1p   = (float*)vp;
    cudaGetSymbolAddress(&vp, g_z1);     z1p    = (float*)vp;
    cudaGetSymbolAddress(&vp, g_out1);   out1p  = (float*)vp;
    cudaGetSymbolAddress(&vp, g_h1);     h1p    = (float*)vp;
    cudaGetSymbolAddress(&vp, g_h2feat); h2feat = (float*)vp;
    cudaGetSymbolAddress(&vp, g_as2);    as2p   = (float*)vp;
    cudaGetSymbolAddress(&vp, g_ad2);    ad2p   = (float*)vp;
    cudaGetSymbolAddress(&vp, g_z2);     z2p    = (float*)vp;
    cudaGetSymbolAddress(&vp, g_out2);   out2p  = (float*)vp;

    float *alpha1, *alpha2;
    if (full) {
        alpha1 = out + SZ_LOG + SZ_EI;
        alpha2 = alpha1 + SZ_A;
    } else {
        cudaGetSymbolAddress(&vp, g_alpha1s); alpha1 = (float*)vp;
        cudaGetSymbolAddress(&vp, g_alpha2s); alpha2 = (float*)vp;
    }

    k_detect<<<1, 32>>>(ei);
    k_zero<<<(NN * 32 + 255) / 256, 256>>>();

    // layer 1
    {
        dim3 g(256 / 64, (NN + 127) / 128);
        sgemm_nt<<<g, 256>>>(x, W1, h1feat, NN, 256, 128);
    }
    {
        int blocks = (NN * 8 + 31) / 32;   // P=32 pairs per block
        k_attn2<32, 3><<<blocks, 256>>>((const float4*)h1feat, aS1, aD1, as1p, ad1p);
    }
    k_passB<<<(ETOT + 255) / 256, 256>>>(ei, as1p, ad1p, alpha1, z1p);
    {
        long long thr = (long long)ETOT * 32;
        k_passC32<<<(int)((thr + 255) / 256), 256>>>(ei, h1feat, z1p, alpha1, out1p);
    }
    k_fin1<<<(NN * 32 + 255) / 256, 256>>>(b1);

    // layer 2
    {
        dim3 g(128 / 64, (NN + 127) / 128);
        sgemm_nt<<<g, 256>>>(h1p, W2, h2feat, NN, 128, 32);
    }
    {
        int blocks = (NN * 8 + 63) / 64;   // P=64 pairs per block
        k_attn2<16, 2><<<blocks, 256>>>((const float4*)h2feat, aS2, aD2, as2p, ad2p);
    }
    k_passB<<<(ETOT + 255) / 256, 256>>>(ei, as2p, ad2p, alpha2, z2p);
    {
        long long thr = (long long)ETOT * 16;
        k_passC16<<<(int)((thr + 255) / 256), 256>>>(ei, h2feat, z2p, alpha2, out2p);
    }
    k_fin2<<<(NN + 255) / 256, 256>>>(b2, out);

    if (full) k_ei<<<(2 * ETOT + 255) / 256, 256>>>(ei, out + SZ_LOG);
}

// round 5
// speedup vs baseline: 1.4068x; 1.0023x over previous
#include <cuda_runtime.h>
#include <math.h>

#define NN 100000
#define EE 800000
#define ETOT 900000   // EE + NN self loops

// ---------------- device scratch (no cudaMalloc allowed) ----------------
__device__ int   g_is64;
__device__ float g_h1feat[NN * 256];   // layer1 per-head features [N, 8*32]
__device__ float g_as1[NN * 8];
__device__ float g_ad1[NN * 8];
__device__ float g_z1[NN * 8];
__device__ float g_out1[NN * 32];
__device__ float g_h1[NN * 32];
__device__ float g_h2feat[NN * 128];   // layer2 per-head features [N, 8*16]
__device__ float g_as2[NN * 8];
__device__ float g_ad2[NN * 8];
__device__ float g_z2[NN * 8];
__device__ float g_out2[NN * 16];
__device__ float g_alpha1s[ETOT * 8];
__device__ float g_alpha2s[ETOT * 8];

// ---------------- int64/int32 edge-index autodetect ----------------
__global__ void k_detect(const void* ei) {
    if (blockIdx.x == 0 && threadIdx.x == 0) {
        const long long* p = (const long long*)ei;
        int ok = 1;
        for (int i = 0; i < 8; i++) {
            long long v = p[i];
            if (v < 0 || v >= NN) ok = 0;
        }
        g_is64 = ok;
    }
}

__device__ __forceinline__ int ld_idx(const void* ei, long long pos) {
    if (g_is64) return (int)((const long long*)ei)[pos];
    return ((const int*)ei)[pos];
}

__global__ void k_zero() {
    int i = blockIdx.x * blockDim.x + threadIdx.x;
    if (i < NN * 8)  { g_z1[i] = 0.f; g_z2[i] = 0.f; }
    if (i < NN * 32)   g_out1[i] = 0.f;
    if (i < NN * 16)   g_out2[i] = 0.f;
}

// ---------------- SGEMM: C[M,Nc] = A[M,K] * B[Nc,K]^T ----------------
// BM=128, BN=64, BK=16, 256 threads, 8x4 per-thread microtile.
__global__ __launch_bounds__(256) void sgemm_nt(
        const float* __restrict__ A, const float* __restrict__ B,
        float* __restrict__ C, int M, int Nc, int K) {
    __shared__ float As[16][132];   // [k][row]
    __shared__ float Bs[16][68];    // [k][col]
    int bm = blockIdx.y * 128, bn = blockIdx.x * 64;
    int tid = threadIdx.x;
    int tx = tid & 15;              // col group (4 cols)
    int ty = tid >> 4;              // row group (8 rows)

    float acc[8][4];
#pragma unroll
    for (int i = 0; i < 8; i++)
#pragma unroll
        for (int j = 0; j < 4; j++) acc[i][j] = 0.f;

    for (int k0 = 0; k0 < K; k0 += 16) {
        // load A tile: 128 rows x 16 k = 512 float4; 2 per thread
#pragma unroll
        for (int t = 0; t < 2; t++) {
            int f = tid * 2 + t;
            int r = f >> 2, kc = (f & 3) << 2;
            float4 v = make_float4(0.f, 0.f, 0.f, 0.f);
            int arow = bm + r;
            if (arow < M) v = *(const float4*)(A + (size_t)arow * K + k0 + kc);
            As[kc + 0][r] = v.x; As[kc + 1][r] = v.y;
            As[kc + 2][r] = v.z; As[kc + 3][r] = v.w;
        }
        // load B tile: 64 rows x 16 k = 256 float4; 1 per thread
        {
            int r = tid >> 2, kc = (tid & 3) << 2;
            float4 v = *(const float4*)(B + (size_t)(bn + r) * K + k0 + kc);
            Bs[kc + 0][r] = v.x; Bs[kc + 1][r] = v.y;
            Bs[kc + 2][r] = v.z; Bs[kc + 3][r] = v.w;
        }
        __syncthreads();
#pragma unroll
        for (int k = 0; k < 16; k++) {
            float a[8], b[4];
            float4 a0 = *(const float4*)&As[k][ty * 8];
            float4 a1 = *(const float4*)&As[k][ty * 8 + 4];
            a[0] = a0.x; a[1] = a0.y; a[2] = a0.z; a[3] = a0.w;
            a[4] = a1.x; a[5] = a1.y; a[6] = a1.z; a[7] = a1.w;
            float4 bv = *(const float4*)&Bs[k][tx * 4];
            b[0] = bv.x; b[1] = bv.y; b[2] = bv.z; b[3] = bv.w;
#pragma unroll
            for (int i = 0; i < 8; i++)
#pragma unroll
                for (int j = 0; j < 4; j++) acc[i][j] += a[i] * b[j];
        }
        __syncthreads();
    }
#pragma unroll
    for (int i = 0; i < 8; i++) {
        int row = bm + ty * 8 + i;
        if (row < M) {
            float4 v = make_float4(acc[i][0], acc[i][1], acc[i][2], acc[i][3]);
            *(float4*)(C + (size_t)row * Nc + bn + tx * 4) = v;
        }
    }
}

// ---------------- attention coefficients (coalesced float4 + butterfly) ----------------
// G = F/4 threads per (node,head) pair. LG2G = log2(G).
template <int F, int LG2G>
__global__ __launch_bounds__(256) void k_attn2(
        const float4* __restrict__ feat4,
        const float* __restrict__ a_src,
        const float* __restrict__ a_dst,
        float* __restrict__ as_, float* __restrict__ ad_) {
    constexpr int G = F / 4;          // 8 (F=32) or 4 (F=16)
    constexpr int P = 256 / G;        // pairs per block
    __shared__ float4 sa[8 * G], sd[8 * G];
    int tid = threadIdx.x;
    if (tid < 8 * G) {
        sa[tid] = ((const float4*)a_src)[tid];
        sd[tid] = ((const float4*)a_dst)[tid];
    }
    __syncthreads();
    int pair = blockIdx.x * P + (tid >> LG2G);   // = n*8 + h
    int g = tid & (G - 1);
    bool ok = (pair < NN * 8);
    int h = pair & 7;
    float4 v = make_float4(0.f, 0.f, 0.f, 0.f);
    if (ok) v = feat4[(size_t)pair * G + g];
    float4 A = sa[h * G + g], D = sd[h * G + g];
    float vs = v.x * A.x + v.y * A.y + v.z * A.z + v.w * A.w;
    float vd = v.x * D.x + v.y * D.y + v.z * D.z + v.w * D.w;
#pragma unroll
    for (int off = G / 2; off > 0; off >>= 1) {
        vs += __shfl_xor_sync(0xffffffffu, vs, off);
        vd += __shfl_xor_sync(0xffffffffu, vd, off);
    }
    if (ok && g == 0) { as_[pair] = vs; ad_[pair] = vd; }
}

// ---------------- pass B ----------------
__global__ void k_passB(const void* ei, const float* __restrict__ as_,
                        const float* __restrict__ ad_, float* __restrict__ alpha,
                        float* __restrict__ z) {
    int e = blockIdx.x * blockDim.x + threadIdx.x;
    if (e >= ETOT) return;
    int s, d;
    if (e < EE) { s = ld_idx(ei, e); d = ld_idx(ei, EE + e); }
    else        { s = e - EE; d = s; }
    const float* ap = as_ + (size_t)s * 8;
    const float* dp = ad_ + (size_t)d * 8;
    float p[8];
#pragma unroll
    for (int h = 0; h < 8; h++) {
        float x = ap[h] + dp[h];
        x = x > 0.f ? x : 0.2f * x;
        p[h] = __expf(x);
    }
#pragma unroll
    for (int h = 0; h < 8; h++) alpha[(size_t)e * 8 + h] = p[h];
    float* zp = z + (size_t)d * 8;
#pragma unroll
    for (int h = 0; h < 8; h++) atomicAdd(zp + h, p[h]);
}

// ---------------- pass C, F=32: warp per edge ----------------
__global__ void k_passC32(const void* ei, const float* __restrict__ feat,
                          const float* __restrict__ z, float* __restrict__ alpha,
                          float* __restrict__ outacc) {
    int e = (blockIdx.x * blockDim.x + threadIdx.x) >> 5;
    int lane = threadIdx.x & 31;
    if (e >= ETOT) return;
    int s, d;
    if (e < EE) { s = ld_idx(ei, e); d = ld_idx(ei, EE + e); }
    else        { s = e - EE; d = s; }
    float a = 0.f;
    if (lane < 8) {
        float p = alpha[(size_t)e * 8 + lane];
        float zz = z[(size_t)d * 8 + lane];
        a = p / (zz + 1e-16f);
        alpha[(size_t)e * 8 + lane] = a;
    }
    float ah[8];
#pragma unroll
    for (int h = 0; h < 8; h++) ah[h] = __shfl_sync(0xffffffffu, a, h);
    const float* fp = feat + (size_t)s * 256;
    float acc = 0.f;
#pragma unroll
    for (int h = 0; h < 8; h++) acc += ah[h] * fp[h * 32 + lane];
    atomicAdd(outacc + (size_t)d * 32 + lane, acc);
}

// ---------------- pass C, F=16: two edges per warp (16 lanes each) ----------------
__global__ void k_passC16(const void* ei, const float* __restrict__ feat,
                          const float* __restrict__ z, float* __restrict__ alpha,
                          float* __restrict__ outacc) {
    int gt = blockIdx.x * blockDim.x + threadIdx.x;
    int e = gt >> 4;                 // 16 lanes per edge
    int l = threadIdx.x & 15;
    int sub = (threadIdx.x >> 4) & 1;
    if (e >= ETOT) return;
    int s, d;
    if (e < EE) { s = ld_idx(ei, e); d = ld_idx(ei, EE + e); }
    else        { s = e - EE; d = s; }
    float a = 0.f;
    if (l < 8) {
        float p = alpha[(size_t)e * 8 + l];
        float zz = z[(size_t)d * 8 + l];
        a = p / (zz + 1e-16f);
        alpha[(size_t)e * 8 + l] = a;
    }
    float ah[8];
    int base = sub << 4;
#pragma unroll
    for (int h = 0; h < 8; h++) ah[h] = __shfl_sync(0xffffffffu, a, base + h);
    const float* fp = feat + (size_t)s * 128;
    float acc = 0.f;
#pragma unroll
    for (int h = 0; h < 8; h++) acc += ah[h] * fp[h * 16 + l];
    atomicAdd(outacc + (size_t)d * 16 + l, acc);
}

// ---------------- finalize layer 1 ----------------
__global__ void k_fin1(const float* __restrict__ b1) {
    int i = blockIdx.x * blockDim.x + threadIdx.x;
    if (i >= NN * 32) return;
    float v = g_out1[i] * 0.125f + b1[i & 31];
    g_h1[i] = v > 0.f ? v : 0.f;
}

// ---------------- finalize layer 2: log_softmax ----------------
__global__ void k_fin2(const float* __restrict__ b2, float* __restrict__ outlog) {
    int n = blockIdx.x * blockDim.x + threadIdx.x;
    if (n >= NN) return;
    float v[16];
    float m = -1e30f;
#pragma unroll
    for (int j = 0; j < 16; j++) {
        v[j] = g_out2[n * 16 + j] * 0.125f + b2[j];
        m = fmaxf(m, v[j]);
    }
    float sum = 0.f;
#pragma unroll
    for (int j = 0; j < 16; j++) sum += expf(v[j] - m);
    float lse = m + logf(sum);
#pragma unroll
    for (int j = 0; j < 16; j++) outlog[n * 16 + j] = v[j] - lse;
}

// ---------------- emit ei_loops as float ----------------
__global__ void k_ei(const void* ei, float* __restrict__ o) {
    int i = blockIdx.x * blockDim.x + threadIdx.x;
    if (i >= 2 * ETOT) return;
    int row = i / ETOT;
    int e = i - row * ETOT;
    long long v;
    if (e < EE) v = ld_idx(ei, (long long)row * EE + e);
    else        v = e - EE;
    o[i] = (float)v;
}

// ---------------- host launcher ----------------
extern "C" void kernel_launch(void* const* d_in, const int* in_sizes, int n_in,
                              void* d_out, int out_size) {
    const float* x    = (const float*)d_in[0];
    const void*  ei   = d_in[1];
    const float* W1   = (const float*)d_in[2];
    const float* aS1  = (const float*)d_in[3];
    const float* aD1  = (const float*)d_in[4];
    const float* b1   = (const float*)d_in[5];
    const float* W2   = (const float*)d_in[6];
    const float* aS2  = (const float*)d_in[7];
    const float* aD2  = (const float*)d_in[8];
    const float* b2   = (const float*)d_in[9];
    float* out = (float*)d_out;

    const long long SZ_LOG = (long long)NN * 16;
    const long long SZ_EI  = 2LL * ETOT;
    const long long SZ_A   = (long long)ETOT * 8;
    const long long FULL   = SZ_LOG + SZ_EI + 2 * SZ_A;
    bool full = ((long long)out_size >= FULL);

    void* vp;
    float *h1feat, *as1p, *ad1p, *z1p, *out1p, *h1p;
    float *h2feat, *as2p, *ad2p, *z2p, *out2p;
    cudaGetSymbolAddress(&vp, g_h1feat); h1feat = (float*)vp;
    cudaGetSymbolAddress(&vp, g_as1);    as1p   = (float*)vp;
    cudaGetSymbolAddress(&vp, g_ad1);    ad1p   = (float*)vp;
    cudaGetSymbolAddress(&vp, g_z1);     z1p    = (float*)vp;
    cudaGetSymbolAddress(&vp, g_out1);   out1p  = (float*)vp;
    cudaGetSymbolAddress(&vp, g_h1);     h1p    = (float*)vp;
    cudaGetSymbolAddress(&vp, g_h2feat); h2feat = (float*)vp;
    cudaGetSymbolAddress(&vp, g_as2);    as2p   = (float*)vp;
    cudaGetSymbolAddress(&vp, g_ad2);    ad2p   = (float*)vp;
    cudaGetSymbolAddress(&vp, g_z2);     z2p    = (float*)vp;
    cudaGetSymbolAddress(&vp, g_out2);   out2p  = (float*)vp;

    float *alpha1, *alpha2;
    if (full) {
        alpha1 = out + SZ_LOG + SZ_EI;
        alpha2 = alpha1 + SZ_A;
    } else {
        cudaGetSymbolAddress(&vp, g_alpha1s); alpha1 = (float*)vp;
        cudaGetSymbolAddress(&vp, g_alpha2s); alpha2 = (float*)vp;
    }

    k_detect<<<1, 32>>>(ei);
    k_zero<<<(NN * 32 + 255) / 256, 256>>>();

    // layer 1
    {
        dim3 g(256 / 64, (NN + 127) / 128);
        sgemm_nt<<<g, 256>>>(x, W1, h1feat, NN, 256, 128);
    }
    {
        int blocks = (NN * 8 + 31) / 32;   // P=32 pairs per block
        k_attn2<32, 3><<<blocks, 256>>>((const float4*)h1feat, aS1, aD1, as1p, ad1p);
    }
    k_passB<<<(ETOT + 255) / 256, 256>>>(ei, as1p, ad1p, alpha1, z1p);
    {
        long long thr = (long long)ETOT * 32;
        k_passC32<<<(int)((thr + 255) / 256), 256>>>(ei, h1feat, z1p, alpha1, out1p);
    }
    k_fin1<<<(NN * 32 + 255) / 256, 256>>>(b1);

    // layer 2
    {
        dim3 g(128 / 64, (NN + 127) / 128);
        sgemm_nt<<<g, 256>>>(h1p, W2, h2feat, NN, 128, 32);
    }
    {
        int blocks = (NN * 8 + 63) / 64;   // P=64 pairs per block
        k_attn2<16, 2><<<blocks, 256>>>((const float4*)h2feat, aS2, aD2, as2p, ad2p);
    }
    k_passB<<<(ETOT + 255) / 256, 256>>>(ei, as2p, ad2p, alpha2, z2p);
    {
        long long thr = (long long)ETOT * 16;
        k_passC16<<<(int)((thr + 255) / 256), 256>>>(ei, h2feat, z2p, alpha2, out2p);
    }
    k_fin2<<<(NN + 255) / 256, 256>>>(b2, out);

    if (full) k_ei<<<(2 * ETOT + 255) / 256, 256>>>(ei, out + SZ_LOG);
}